// round 14
// baseline (speedup 1.0000x reference)
#include <cuda_runtime.h>
#include <cuda_fp16.h>
#include <cstdint>

// ---------------- problem constants ----------------
#define Dc   1024
#define Ec   8
#define Hc   2730
#define HP2  2816            // H padded to 22*128
#define NT   8192
#define TMp  128             // per-expert row padding
#define MMAX (2*NT + Ec*TMp) // 17408
#define KCH  64              // K halves per pipeline chunk (4 x k16)

// smem strides (halves)
#define SA1  72              // A row stride (64 K + 8 pad)  = 144 B
#define SBF1 72              // FFN1 B row stride (64 N + 8 pad)
#define SBF2 136             // FFN2 B row stride (128 N + 8 pad) = 272 B

// FFN1 stage (halves): A[128][72]=9216, B1[64][72]=4608, B3[64][72]=4608
#define F1_B1OFF 9216
#define F1_B3OFF 13824
#define F1_STGH  18432
#define F1_SMEM  (3 * F1_STGH * 2)    // 110592 B  (2 CTAs/SM)
// FFN2 stage: A[128][72]=9216, B[64][136]=8704
#define F2_BOFF  9216
#define F2_STGH  17920
#define F2_SMEM  (3 * F2_STGH * 2)    // 107520 B  (2 CTAs/SM)

// ---------------- device scratch ----------------
__device__ int    g_cnt[Ec];
__device__ int    g_cur[Ec];
__device__ int    g_off[Ec + 1];
__device__ int    g_tok[MMAX];
__device__ float  g_gate[MMAX];
__device__ int    g_topi[NT * 2];
__device__ float  g_topv[NT * 2];
__device__ __half g_w1h[(size_t)Ec * Dc * HP2];   // W1 fp16 [E][Dc][HP2]
__device__ __half g_w3h[(size_t)Ec * Dc * HP2];   // W3 fp16
__device__ __half g_w2h[(size_t)Ec * HP2 * Dc];   // W2 fp16 [E][HP2][Dc]
__device__ __half g_xh[(size_t)NT * Dc];          // x fp16
__device__ __half g_h[(size_t)MMAX * HP2];        // activations fp16

// ---------------- helpers ----------------
__device__ __forceinline__ uint32_t smem_u32(const void* p) {
    uint32_t a;
    asm("{ .reg .u64 t; cvta.to.shared.u64 t, %1; cvt.u32.u64 %0, t; }" : "=r"(a) : "l"(p));
    return a;
}
#define CP16(dst, src) asm volatile("cp.async.cg.shared.global [%0], [%1], 16;" :: "r"(dst), "l"(src) : "memory")
#define CP_COMMIT()    asm volatile("cp.async.commit_group;" ::: "memory")
#define CP_WAIT0()     asm volatile("cp.async.wait_group 0;" ::: "memory")
#define CP_WAIT1()     asm volatile("cp.async.wait_group 1;" ::: "memory")

__device__ __forceinline__ void ldsm_x4(uint32_t* r, uint32_t a) {
    asm volatile("ldmatrix.sync.aligned.m8n8.x4.shared.b16 {%0,%1,%2,%3}, [%4];"
        : "=r"(r[0]), "=r"(r[1]), "=r"(r[2]), "=r"(r[3]) : "r"(a));
}
__device__ __forceinline__ void ldsm_x4t(uint32_t* r, uint32_t a) {
    asm volatile("ldmatrix.sync.aligned.m8n8.x4.trans.shared.b16 {%0,%1,%2,%3}, [%4];"
        : "=r"(r[0]), "=r"(r[1]), "=r"(r[2]), "=r"(r[3]) : "r"(a));
}
__device__ __forceinline__ void mma16(float* d, const uint32_t* a, const uint32_t* b) {
    asm volatile(
        "mma.sync.aligned.m16n8k16.row.col.f32.f16.f16.f32 "
        "{%0,%1,%2,%3}, {%4,%5,%6,%7}, {%8,%9}, {%0,%1,%2,%3};"
        : "+f"(d[0]), "+f"(d[1]), "+f"(d[2]), "+f"(d[3])
        : "r"(a[0]), "r"(a[1]), "r"(a[2]), "r"(a[3]), "r"(b[0]), "r"(b[1]));
}

// ---------------- s1: bookkeeping init ----------------
__global__ void k_init() {
    int i = blockIdx.x * blockDim.x + threadIdx.x;
    if (i < Ec) { g_cnt[i] = 0; g_cur[i] = 0; }
    if (i < MMAX) { g_tok[i] = -1; g_gate[i] = 0.0f; }
}

// ---------------- s0: convert W1,W3 to fp16 + zero out ----------------
__global__ void k_prep13(const float* __restrict__ W1, const float* __restrict__ W3,
                         float* __restrict__ out) {
    {
        float4 z = make_float4(0.f, 0.f, 0.f, 0.f);
        *(float4*)(out + (size_t)blockIdx.x * 1024 + threadIdx.x * 4) = z;
    }
    int row = blockIdx.x;                       // 0 .. E*Dc-1
    const float* i1 = W1 + (size_t)row * Hc;
    const float* i3 = W3 + (size_t)row * Hc;
    __half* o1 = g_w1h + (size_t)row * HP2;
    __half* o3 = g_w3h + (size_t)row * HP2;
    for (int u = threadIdx.x; u < HP2 / 8; u += 256) {
        int j = u * 8;
        __half2 v1[4], v3[4];
        if (j + 8 <= Hc) {
            float2 a0 = *(const float2*)(i1 + j),     a1 = *(const float2*)(i1 + j + 2);
            float2 a2 = *(const float2*)(i1 + j + 4), a3 = *(const float2*)(i1 + j + 6);
            v1[0] = __floats2half2_rn(a0.x, a0.y); v1[1] = __floats2half2_rn(a1.x, a1.y);
            v1[2] = __floats2half2_rn(a2.x, a2.y); v1[3] = __floats2half2_rn(a3.x, a3.y);
            float2 b0 = *(const float2*)(i3 + j),     b1 = *(const float2*)(i3 + j + 2);
            float2 b2 = *(const float2*)(i3 + j + 4), b3 = *(const float2*)(i3 + j + 6);
            v3[0] = __floats2half2_rn(b0.x, b0.y); v3[1] = __floats2half2_rn(b1.x, b1.y);
            v3[2] = __floats2half2_rn(b2.x, b2.y); v3[3] = __floats2half2_rn(b3.x, b3.y);
        } else {
#pragma unroll
            for (int t = 0; t < 4; t++) {
                int c0 = j + 2 * t, c1 = j + 2 * t + 1;
                float f0 = (c0 < Hc) ? i1[c0] : 0.f;
                float f1 = (c1 < Hc) ? i1[c1] : 0.f;
                v1[t] = __floats2half2_rn(f0, f1);
                float g0 = (c0 < Hc) ? i3[c0] : 0.f;
                float g1 = (c1 < Hc) ? i3[c1] : 0.f;
                v3[t] = __floats2half2_rn(g0, g1);
            }
        }
        *(uint4*)(o1 + j) = *(uint4*)v1;
        *(uint4*)(o3 + j) = *(uint4*)v3;
    }
}

// ---------------- s1: convert W2 to fp16 (row-padded), overlaps FFN1 ----------------
__global__ void k_w2h(const float* __restrict__ in) {
    int row = blockIdx.x;                       // 0 .. E*HP2-1
    int e = row / HP2, hp = row % HP2;
    __half* op = g_w2h + (size_t)row * Dc;
    int j = threadIdx.x * 8;
    __half2 v[4];
    if (hp < Hc) {
        const float* ip = in + ((size_t)e * Hc + hp) * Dc + j;
        float4 a = *(const float4*)ip, b = *(const float4*)(ip + 4);
        v[0] = __floats2half2_rn(a.x, a.y); v[1] = __floats2half2_rn(a.z, a.w);
        v[2] = __floats2half2_rn(b.x, b.y); v[3] = __floats2half2_rn(b.z, b.w);
    } else {
        v[0] = v[1] = v[2] = v[3] = __floats2half2_rn(0.f, 0.f);
    }
    *(uint4*)(op + j) = *(uint4*)v;
}

// ---------------- s1: router (+ x -> fp16) ----------------
__global__ void k_routerx(const float* __restrict__ x, const float* __restrict__ Wr) {
    int warp = threadIdx.x >> 5, lane = threadIdx.x & 31;
    int n = blockIdx.x * 8 + warp;
    if (n >= NT) return;
    const float* xr = x + (size_t)n * Dc;
    __half* xo = g_xh + (size_t)n * Dc;
    float acc[Ec];
#pragma unroll
    for (int e = 0; e < Ec; e++) acc[e] = 0.0f;
    for (int d0 = lane * 4; d0 < Dc; d0 += 128) {
        float4 xv = *(const float4*)(xr + d0);
        __half2 h01 = __floats2half2_rn(xv.x, xv.y);
        __half2 h23 = __floats2half2_rn(xv.z, xv.w);
        uint2 pk;
        pk.x = *(uint32_t*)&h01; pk.y = *(uint32_t*)&h23;
        *(uint2*)(xo + d0) = pk;
        float xs[4] = {xv.x, xv.y, xv.z, xv.w};
#pragma unroll
        for (int j = 0; j < 4; j++) {
            float4 w0 = *(const float4*)(Wr + (d0 + j) * Ec);
            float4 w1 = *(const float4*)(Wr + (d0 + j) * Ec + 4);
            acc[0] += xs[j] * w0.x; acc[1] += xs[j] * w0.y;
            acc[2] += xs[j] * w0.z; acc[3] += xs[j] * w0.w;
            acc[4] += xs[j] * w1.x; acc[5] += xs[j] * w1.y;
            acc[6] += xs[j] * w1.z; acc[7] += xs[j] * w1.w;
        }
    }
#pragma unroll
    for (int e = 0; e < Ec; e++)
#pragma unroll
        for (int o = 16; o > 0; o >>= 1)
            acc[e] += __shfl_xor_sync(0xffffffffu, acc[e], o);
    if (lane == 0) {
        float mx = acc[0];
#pragma unroll
        for (int e = 1; e < Ec; e++) mx = fmaxf(mx, acc[e]);
        float p[Ec], s = 0.0f;
#pragma unroll
        for (int e = 0; e < Ec; e++) { p[e] = __expf(acc[e] - mx); s += p[e]; }
        float inv = 1.0f / s;
        int i1 = 0;
#pragma unroll
        for (int e = 1; e < Ec; e++) if (p[e] > p[i1]) i1 = e;
        int i2 = (i1 == 0) ? 1 : 0;
#pragma unroll
        for (int e = 0; e < Ec; e++) if (e != i1 && p[e] > p[i2]) i2 = e;
        g_topi[2 * n] = i1;     g_topv[2 * n] = p[i1] * inv;
        g_topi[2 * n + 1] = i2; g_topv[2 * n + 1] = p[i2] * inv;
        atomicAdd(&g_cnt[i1], 1);
        atomicAdd(&g_cnt[i2], 1);
    }
}

// ---------------- s1: fused scan + scatter ----------------
__global__ void k_scansc() {
    __shared__ int soff[Ec];
    if (threadIdx.x == 0) {
        int o = 0;
#pragma unroll
        for (int e = 0; e < Ec; e++) {
            soff[e] = o;
            o += ((g_cnt[e] + TMp - 1) / TMp) * TMp;
        }
        if (blockIdx.x == 0) {
#pragma unroll
            for (int e = 0; e < Ec; e++) g_off[e] = soff[e];
            g_off[Ec] = o;
        }
    }
    __syncthreads();
    int n = blockIdx.x * blockDim.x + threadIdx.x;
    if (n >= NT) return;
#pragma unroll
    for (int k = 0; k < 2; k++) {
        int e = g_topi[2 * n + k];
        int pos = soff[e] + atomicAdd(&g_cur[e], 1);
        g_tok[pos] = n;
        g_gate[pos] = g_topv[2 * n + k];
    }
}

// ============ s0: FFN1, CTA 128x64, 2 CTA/SM, software-pipelined fragments ============
__global__ void __launch_bounds__(256, 2) k_ffn1() {
    extern __shared__ __half sm[];
    int m0 = blockIdx.y * 128;
    if (m0 >= g_off[Ec]) return;
    int e = 0;
#pragma unroll
    for (int i = 1; i < Ec; i++) if (m0 >= g_off[i]) e = i;
    int n0 = blockIdx.x * 64;

    int tid = threadIdx.x, wid = tid >> 5, lane = tid & 31;
    int wm = wid & 3, wn = wid >> 2;
    int gi = lane >> 2, ti = lane & 3;
    uint32_t smb = smem_u32(sm);

    int rA = tid >> 1, chA = (tid & 1) * 32;
    int rB = tid >> 2, cnB = (tid & 3) * 16;
    int tok = g_tok[m0 + rA];
    const __half* srcA  = g_xh + (size_t)(tok < 0 ? 0 : tok) * Dc + chA;
    const __half* srcB1 = g_w1h + ((size_t)e * Dc + rB) * HP2 + n0 + cnB;
    const __half* srcB3 = g_w3h + ((size_t)e * Dc + rB) * HP2 + n0 + cnB;
    uint32_t dstA  = smb + (uint32_t)(rA * SA1 + chA) * 2;
    uint32_t dstB1 = smb + (uint32_t)(F1_B1OFF + rB * SBF1 + cnB) * 2;
    uint32_t dstB3 = smb + (uint32_t)(F1_B3OFF + rB * SBF1 + cnB) * 2;
    const uint32_t STGB = (uint32_t)F1_STGH * 2;

    auto issue = [&](int kc, int buf) {
        int k0 = kc * KCH;
        uint32_t so = buf * STGB;
        const __half* sA = srcA + k0;
        uint32_t dA = dstA + so;
        CP16(dA, sA); CP16(dA + 16, sA + 8); CP16(dA + 32, sA + 16); CP16(dA + 48, sA + 24);
        const __half* s1 = srcB1 + (size_t)k0 * HP2;
        uint32_t d1 = dstB1 + so;
        CP16(d1, s1); CP16(d1 + 16, s1 + 8);
        const __half* s3 = srcB3 + (size_t)k0 * HP2;
        uint32_t d3 = dstB3 + so;
        CP16(d3, s3); CP16(d3 + 16, s3 + 8);
    };

    int aRow = wm * 32 + (lane & 7) + 8 * ((lane >> 3) & 1);
    uint32_t aBase = smb + (uint32_t)(aRow * SA1 + 8 * (lane >> 4)) * 2;
    int bRowK = (lane & 7) + 8 * ((lane >> 3) & 1);
    uint32_t bBase = smb + (uint32_t)(F1_B1OFF + bRowK * SBF1 + wn * 32 + (lane >> 4) * 8) * 2;
    const uint32_t B3D = (uint32_t)(F1_B3OFF - F1_B1OFF) * 2;   // 9216

    float acc1[2][4][4], acc3[2][4][4];
#pragma unroll
    for (int mt = 0; mt < 2; mt++)
#pragma unroll
        for (int nt = 0; nt < 4; nt++)
#pragma unroll
            for (int j = 0; j < 4; j++) { acc1[mt][nt][j] = 0.f; acc3[mt][nt][j] = 0.f; }

    const int nc = Dc / KCH;   // 16
    issue(0, 0); CP_COMMIT();
    issue(1, 1); CP_COMMIT();

    // ping-pong fragment banks
    uint32_t afp[2][2][4];
    uint32_t b1p[2][2][4];
    uint32_t b3p[2][2][4];

    for (int c = 0; c < nc; ++c) {
        if (c + 1 < nc) CP_WAIT1(); else CP_WAIT0();
        __syncthreads();
        if (c + 2 < nc) { issue(c + 2, (c + 2) % 3); CP_COMMIT(); }
        uint32_t so = (uint32_t)(c % 3) * STGB;
        uint32_t aA = aBase + so;
        uint32_t bB = bBase + so;

        // prologue: load ks=0 fragments into bank 0
        ldsm_x4(afp[0][0], aA);
        ldsm_x4(afp[0][1], aA + 2304);
#pragma unroll
        for (int np = 0; np < 2; np++) {
            uint32_t bo = bB + np * 32;
            ldsm_x4t(b1p[0][np], bo);
            ldsm_x4t(b3p[0][np], bo + B3D);
        }

#pragma unroll
        for (int ks = 0; ks < 4; ks++) {
            const int cur = ks & 1, nxt = cur ^ 1;
            if (ks < 3) {
                // prefetch ks+1 fragments into the other bank
                ldsm_x4(afp[nxt][0], aA + (ks + 1) * 32);
                ldsm_x4(afp[nxt][1], aA + 2304 + (ks + 1) * 32);
#pragma unroll
                for (int np = 0; np < 2; np++) {
                    uint32_t bo = bB + (ks + 1) * 2304 + np * 32;
                    ldsm_x4t(b1p[nxt][np], bo);
                    ldsm_x4t(b3p[nxt][np], bo + B3D);
                }
            }
#pragma unroll
            for (int np = 0; np < 2; np++) {
                mma16(acc1[0][2 * np],     afp[cur][0], b1p[cur][np]);
                mma16(acc1[1][2 * np],     afp[cur][1], b1p[cur][np]);
                mma16(acc1[0][2 * np + 1], afp[cur][0], b1p[cur][np] + 2);
                mma16(acc1[1][2 * np + 1], afp[cur][1], b1p[cur][np] + 2);
                mma16(acc3[0][2 * np],     afp[cur][0], b3p[cur][np]);
                mma16(acc3[1][2 * np],     afp[cur][1], b3p[cur][np]);
                mma16(acc3[0][2 * np + 1], afp[cur][0], b3p[cur][np] + 2);
                mma16(acc3[1][2 * np + 1], afp[cur][1], b3p[cur][np] + 2);
            }
        }
    }

    // epilogue: silu(d1)*d3 -> g_h (fp16)
#pragma unroll
    for (int mt = 0; mt < 2; mt++) {
#pragma unroll
        for (int nt = 0; nt < 4; nt++) {
            int row = m0 + wm * 32 + mt * 16 + gi;
            int col = n0 + wn * 32 + nt * 8 + 2 * ti;
            const float* d1 = acc1[mt][nt];
            const float* d3 = acc3[mt][nt];
            float h0 = d1[0] / (1.0f + __expf(-d1[0])) * d3[0];
            float h1 = d1[1] / (1.0f + __expf(-d1[1])) * d3[1];
            float h2 = d1[2] / (1.0f + __expf(-d1[2])) * d3[2];
            float h3 = d1[3] / (1.0f + __expf(-d1[3])) * d3[3];
            *(__half2*)(g_h + (size_t)row * HP2 + col)       = __floats2half2_rn(h0, h1);
            *(__half2*)(g_h + (size_t)(row + 8) * HP2 + col) = __floats2half2_rn(h2, h3);
        }
    }
}

// ============ s0: FFN2  out += gate * (h @ W2), CTA 128x128, 2 CTA/SM, pipelined ============
__global__ void __launch_bounds__(256, 2) k_ffn2(float* __restrict__ out) {
    extern __shared__ __half sm[];
    int m0 = blockIdx.y * 128;
    if (m0 >= g_off[Ec]) return;
    int e = 0;
#pragma unroll
    for (int i = 1; i < Ec; i++) if (m0 >= g_off[i]) e = i;
    int n0 = blockIdx.x * 128;

    int tid = threadIdx.x, wid = tid >> 5, lane = tid & 31;
    int wm = wid & 3, wn = wid >> 2;
    int gi = lane >> 2, ti = lane & 3;
    uint32_t smb = smem_u32(sm);

    int rA = tid >> 1, chA = (tid & 1) * 32;
    int rB = tid >> 2, cnB = (tid & 3) * 32;
    const __half* srcA = g_h + (size_t)(m0 + rA) * HP2 + chA;
    const __half* srcB = g_w2h + ((size_t)e * HP2 + rB) * Dc + n0 + cnB;
    uint32_t dstA = smb + (uint32_t)(rA * SA1 + chA) * 2;
    uint32_t dstB = smb + (uint32_t)(F2_BOFF + rB * SBF2 + cnB) * 2;
    const uint32_t STGB = (uint32_t)F2_STGH * 2;

    auto issue = [&](int kc, int buf) {
        int k0 = kc * KCH;
        uint32_t so = buf * STGB;
        const __half* sA = srcA + k0;
        uint32_t dA = dstA + so;
        CP16(dA, sA); CP16(dA + 16, sA + 8); CP16(dA + 32, sA + 16); CP16(dA + 48, sA + 24);
        const __half* sB = srcB + (size_t)k0 * Dc;
        uint32_t dB = dstB + so;
        CP16(dB, sB); CP16(dB + 16, sB + 8); CP16(dB + 32, sB + 16); CP16(dB + 48, sB + 24);
    };

    int aRow = wm * 32 + (lane & 7) + 8 * ((lane >> 3) & 1);
    uint32_t aBase = smb + (uint32_t)(aRow * SA1 + 8 * (lane >> 4)) * 2;
    int bRowK = (lane & 7) + 8 * ((lane >> 3) & 1);
    uint32_t bBase = smb + (uint32_t)(F2_BOFF + bRowK * SBF2 + wn * 64 + (lane >> 4) * 8) * 2;

    float acc[2][8][4];
#pragma unroll
    for (int mt = 0; mt < 2; mt++)
#pragma unroll
        for (int nt = 0; nt < 8; nt++)
#pragma unroll
            for (int j = 0; j < 4; j++) acc[mt][nt][j] = 0.f;

    const int nc = HP2 / KCH;   // 44
    issue(0, 0); CP_COMMIT();
    issue(1, 1); CP_COMMIT();

    uint32_t afp[2][2][4];
    uint32_t bfp[2][4][4];

    for (int c = 0; c < nc; ++c) {
        if (c + 1 < nc) CP_WAIT1(); else CP_WAIT0();
        __syncthreads();
        if (c + 2 < nc) { issue(c + 2, (c + 2) % 3); CP_COMMIT(); }
        uint32_t so = (uint32_t)(c % 3) * STGB;
        uint32_t aA = aBase + so;
        uint32_t bB = bBase + so;

        ldsm_x4(afp[0][0], aA);
        ldsm_x4(afp[0][1], aA + 2304);
#pragma unroll
        for (int np = 0; np < 4; np++)
            ldsm_x4t(bfp[0][np], bB + np * 32);

#pragma unroll
        for (int ks = 0; ks < 4; ks++) {
            const int cur = ks & 1, nxt = cur ^ 1;
            if (ks < 3) {
                ldsm_x4(afp[nxt][0], aA + (ks + 1) * 32);
                ldsm_x4(afp[nxt][1], aA + 2304 + (ks + 1) * 32);
#pragma unroll
                for (int np = 0; np < 4; np++)
                    ldsm_x4t(bfp[nxt][np], bB + (ks + 1) * 4352 + np * 32);
            }
#pragma unroll
            for (int np = 0; np < 4; np++) {
                mma16(acc[0][2 * np],     afp[cur][0], bfp[cur][np]);
                mma16(acc[1][2 * np],     afp[cur][1], bfp[cur][np]);
                mma16(acc[0][2 * np + 1], afp[cur][0], bfp[cur][np] + 2);
                mma16(acc[1][2 * np + 1], afp[cur][1], bfp[cur][np] + 2);
            }
        }
    }

    // epilogue: fused combine -> atomicAdd into out[token]
#pragma unroll
    for (int mt = 0; mt < 2; mt++) {
        int row = m0 + wm * 32 + mt * 16 + gi;
        int tok0 = g_tok[row];
        int tok1 = g_tok[row + 8];
        float ga = g_gate[row];
        float gb = g_gate[row + 8];
        float* o0 = out + (size_t)(tok0 < 0 ? 0 : tok0) * Dc;
        float* o1 = out + (size_t)(tok1 < 0 ? 0 : tok1) * Dc;
#pragma unroll
        for (int nt = 0; nt < 8; nt++) {
            int col = n0 + wn * 64 + nt * 8 + 2 * ti;
            const float* d = acc[mt][nt];
            if (tok0 >= 0) {
                atomicAdd(o0 + col,     ga * d[0]);
                atomicAdd(o0 + col + 1, ga * d[1]);
            }
            if (tok1 >= 0) {
                atomicAdd(o1 + col,     gb * d[2]);
                atomicAdd(o1 + col + 1, gb * d[3]);
            }
        }
    }
}

// ---------------- launch: two-stream fork/join ----------------
extern "C" void kernel_launch(void* const* d_in, const int* in_sizes, int n_in,
                              void* d_out, int out_size) {
    const float* x  = (const float*)d_in[0];
    const float* Wr = (const float*)d_in[1];
    const float* W1 = (const float*)d_in[2];
    const float* W2 = (const float*)d_in[3];
    const float* W3 = (const float*)d_in[4];
    float* out = (float*)d_out;

    static cudaStream_t s1 = nullptr;
    static cudaEvent_t e0 = nullptr, e1 = nullptr, e2 = nullptr;
    if (s1 == nullptr) {
        cudaStreamCreateWithFlags(&s1, cudaStreamNonBlocking);
        cudaEventCreateWithFlags(&e0, cudaEventDisableTiming);
        cudaEventCreateWithFlags(&e1, cudaEventDisableTiming);
        cudaEventCreateWithFlags(&e2, cudaEventDisableTiming);
        cudaFuncSetAttribute(k_ffn1, cudaFuncAttributeMaxDynamicSharedMemorySize, F1_SMEM);
        cudaFuncSetAttribute(k_ffn2, cudaFuncAttributeMaxDynamicSharedMemorySize, F2_SMEM);
    }

    cudaEventRecord(e0, 0);
    cudaStreamWaitEvent(s1, e0, 0);
    k_init<<<(MMAX + 255) / 256, 256, 0, s1>>>();
    k_routerx<<<NT / 8, 256, 0, s1>>>(x, Wr);
    k_scansc<<<NT / 256, 256, 0, s1>>>();
    cudaEventRecord(e1, s1);
    k_w2h<<<Ec * HP2, 128, 0, s1>>>(W2);
    cudaEventRecord(e2, s1);

    k_prep13<<<Ec * Dc, 256>>>(W1, W3, out);
    cudaStreamWaitEvent(0, e1, 0);
    k_ffn1<<<dim3(HP2 / 64, MMAX / 128), 256, F1_SMEM>>>();
    cudaStreamWaitEvent(0, e2, 0);
    k_ffn2<<<dim3(Dc / 128, MMAX / 128), 256, F2_SMEM>>>(out);
}

// round 15
// speedup vs baseline: 1.0225x; 1.0225x over previous
#include <cuda_runtime.h>
#include <cuda_fp16.h>
#include <cstdint>

// ---------------- problem constants ----------------
#define Dc   1024
#define Ec   8
#define Hc   2730
#define HP2  2816            // H padded to 22*128
#define NT   8192
#define TMp  128             // per-expert row padding
#define MMAX (2*NT + Ec*TMp) // 17408
#define KCH  64              // K halves per pipeline chunk (4 x k16)

// smem strides (halves)
#define SA1  72              // A row stride (64 K + 8 pad)  = 144 B
#define SBF1 72              // FFN1 B row stride (64 N + 8 pad)
#define SBF2 136             // FFN2 B row stride (128 N + 8 pad) = 272 B

// FFN1 stage (halves): A[128][72]=9216, B1[64][72]=4608, B3[64][72]=4608
#define F1_B1OFF 9216
#define F1_B3OFF 13824
#define F1_STGH  18432
#define F1_SMEM  (3 * F1_STGH * 2)    // 110592 B  (2 CTAs/SM)
// FFN2 stage: A[128][72]=9216, B[64][136]=8704
#define F2_BOFF  9216
#define F2_STGH  17920
#define F2_SMEM  (3 * F2_STGH * 2)    // 107520 B  (2 CTAs/SM)

// ---------------- device scratch ----------------
__device__ int    g_cnt[Ec];
__device__ int    g_cur[Ec];
__device__ int    g_off[Ec + 1];
__device__ int    g_tok[MMAX];
__device__ float  g_gate[MMAX];
__device__ int    g_topi[NT * 2];
__device__ float  g_topv[NT * 2];
__device__ __half g_w1h[(size_t)Ec * Dc * HP2];   // W1 fp16 [E][Dc][HP2]
__device__ __half g_w3h[(size_t)Ec * Dc * HP2];   // W3 fp16
__device__ __half g_w2h[(size_t)Ec * HP2 * Dc];   // W2 fp16 [E][HP2][Dc]
__device__ __half g_xh[(size_t)NT * Dc];          // x fp16
__device__ __half g_h[(size_t)MMAX * HP2];        // activations fp16

// ---------------- helpers ----------------
__device__ __forceinline__ uint32_t smem_u32(const void* p) {
    uint32_t a;
    asm("{ .reg .u64 t; cvta.to.shared.u64 t, %1; cvt.u32.u64 %0, t; }" : "=r"(a) : "l"(p));
    return a;
}
#define CP16(dst, src) asm volatile("cp.async.cg.shared.global [%0], [%1], 16;" :: "r"(dst), "l"(src) : "memory")
#define CP_COMMIT()    asm volatile("cp.async.commit_group;" ::: "memory")
#define CP_WAIT0()     asm volatile("cp.async.wait_group 0;" ::: "memory")
#define CP_WAIT1()     asm volatile("cp.async.wait_group 1;" ::: "memory")

__device__ __forceinline__ void ldsm_x4(uint32_t* r, uint32_t a) {
    asm volatile("ldmatrix.sync.aligned.m8n8.x4.shared.b16 {%0,%1,%2,%3}, [%4];"
        : "=r"(r[0]), "=r"(r[1]), "=r"(r[2]), "=r"(r[3]) : "r"(a));
}
__device__ __forceinline__ void ldsm_x4t(uint32_t* r, uint32_t a) {
    asm volatile("ldmatrix.sync.aligned.m8n8.x4.trans.shared.b16 {%0,%1,%2,%3}, [%4];"
        : "=r"(r[0]), "=r"(r[1]), "=r"(r[2]), "=r"(r[3]) : "r"(a));
}
__device__ __forceinline__ void mma16(float* d, const uint32_t* a, const uint32_t* b) {
    asm volatile(
        "mma.sync.aligned.m16n8k16.row.col.f32.f16.f16.f32 "
        "{%0,%1,%2,%3}, {%4,%5,%6,%7}, {%8,%9}, {%0,%1,%2,%3};"
        : "+f"(d[0]), "+f"(d[1]), "+f"(d[2]), "+f"(d[3])
        : "r"(a[0]), "r"(a[1]), "r"(a[2]), "r"(a[3]), "r"(b[0]), "r"(b[1]));
}

// ---------------- s1: bookkeeping init ----------------
__global__ void k_init() {
    int i = blockIdx.x * blockDim.x + threadIdx.x;
    if (i < Ec) { g_cnt[i] = 0; g_cur[i] = 0; }
    if (i < MMAX) { g_tok[i] = -1; g_gate[i] = 0.0f; }
}

// ---------------- s1: zero out (overlaps FFN1; must precede FFN2) ----------------
__global__ void k_zero(float* __restrict__ out) {
    float4 z = make_float4(0.f, 0.f, 0.f, 0.f);
    *(float4*)(out + (size_t)(blockIdx.x * blockDim.x + threadIdx.x) * 4) = z;
}

// ---------------- s0: convert W1,W3 to fp16 ----------------
__global__ void k_prep13(const float* __restrict__ W1, const float* __restrict__ W3) {
    int row = blockIdx.x;                       // 0 .. E*Dc-1
    const float* i1 = W1 + (size_t)row * Hc;
    const float* i3 = W3 + (size_t)row * Hc;
    __half* o1 = g_w1h + (size_t)row * HP2;
    __half* o3 = g_w3h + (size_t)row * HP2;
    for (int u = threadIdx.x; u < HP2 / 8; u += 256) {
        int j = u * 8;
        __half2 v1[4], v3[4];
        if (j + 8 <= Hc) {
            float2 a0 = *(const float2*)(i1 + j),     a1 = *(const float2*)(i1 + j + 2);
            float2 a2 = *(const float2*)(i1 + j + 4), a3 = *(const float2*)(i1 + j + 6);
            v1[0] = __floats2half2_rn(a0.x, a0.y); v1[1] = __floats2half2_rn(a1.x, a1.y);
            v1[2] = __floats2half2_rn(a2.x, a2.y); v1[3] = __floats2half2_rn(a3.x, a3.y);
            float2 b0 = *(const float2*)(i3 + j),     b1 = *(const float2*)(i3 + j + 2);
            float2 b2 = *(const float2*)(i3 + j + 4), b3 = *(const float2*)(i3 + j + 6);
            v3[0] = __floats2half2_rn(b0.x, b0.y); v3[1] = __floats2half2_rn(b1.x, b1.y);
            v3[2] = __floats2half2_rn(b2.x, b2.y); v3[3] = __floats2half2_rn(b3.x, b3.y);
        } else {
#pragma unroll
            for (int t = 0; t < 4; t++) {
                int c0 = j + 2 * t, c1 = j + 2 * t + 1;
                float f0 = (c0 < Hc) ? i1[c0] : 0.f;
                float f1 = (c1 < Hc) ? i1[c1] : 0.f;
                v1[t] = __floats2half2_rn(f0, f1);
                float g0 = (c0 < Hc) ? i3[c0] : 0.f;
                float g1 = (c1 < Hc) ? i3[c1] : 0.f;
                v3[t] = __floats2half2_rn(g0, g1);
            }
        }
        *(uint4*)(o1 + j) = *(uint4*)v1;
        *(uint4*)(o3 + j) = *(uint4*)v3;
    }
}

// ---------------- s1: convert W2 to fp16 (row-padded), overlaps FFN1 ----------------
__global__ void k_w2h(const float* __restrict__ in) {
    int row = blockIdx.x;                       // 0 .. E*HP2-1
    int e = row / HP2, hp = row % HP2;
    __half* op = g_w2h + (size_t)row * Dc;
    int j = threadIdx.x * 8;
    __half2 v[4];
    if (hp < Hc) {
        const float* ip = in + ((size_t)e * Hc + hp) * Dc + j;
        float4 a = *(const float4*)ip, b = *(const float4*)(ip + 4);
        v[0] = __floats2half2_rn(a.x, a.y); v[1] = __floats2half2_rn(a.z, a.w);
        v[2] = __floats2half2_rn(b.x, b.y); v[3] = __floats2half2_rn(b.z, b.w);
    } else {
        v[0] = v[1] = v[2] = v[3] = __floats2half2_rn(0.f, 0.f);
    }
    *(uint4*)(op + j) = *(uint4*)v;
}

// ---------------- s1: router (+ x -> fp16) ----------------
__global__ void k_routerx(const float* __restrict__ x, const float* __restrict__ Wr) {
    int warp = threadIdx.x >> 5, lane = threadIdx.x & 31;
    int n = blockIdx.x * 8 + warp;
    if (n >= NT) return;
    const float* xr = x + (size_t)n * Dc;
    __half* xo = g_xh + (size_t)n * Dc;
    float acc[Ec];
#pragma unroll
    for (int e = 0; e < Ec; e++) acc[e] = 0.0f;
    for (int d0 = lane * 4; d0 < Dc; d0 += 128) {
        float4 xv = *(const float4*)(xr + d0);
        __half2 h01 = __floats2half2_rn(xv.x, xv.y);
        __half2 h23 = __floats2half2_rn(xv.z, xv.w);
        uint2 pk;
        pk.x = *(uint32_t*)&h01; pk.y = *(uint32_t*)&h23;
        *(uint2*)(xo + d0) = pk;
        float xs[4] = {xv.x, xv.y, xv.z, xv.w};
#pragma unroll
        for (int j = 0; j < 4; j++) {
            float4 w0 = *(const float4*)(Wr + (d0 + j) * Ec);
            float4 w1 = *(const float4*)(Wr + (d0 + j) * Ec + 4);
            acc[0] += xs[j] * w0.x; acc[1] += xs[j] * w0.y;
            acc[2] += xs[j] * w0.z; acc[3] += xs[j] * w0.w;
            acc[4] += xs[j] * w1.x; acc[5] += xs[j] * w1.y;
            acc[6] += xs[j] * w1.z; acc[7] += xs[j] * w1.w;
        }
    }
#pragma unroll
    for (int e = 0; e < Ec; e++)
#pragma unroll
        for (int o = 16; o > 0; o >>= 1)
            acc[e] += __shfl_xor_sync(0xffffffffu, acc[e], o);
    if (lane == 0) {
        float mx = acc[0];
#pragma unroll
        for (int e = 1; e < Ec; e++) mx = fmaxf(mx, acc[e]);
        float p[Ec], s = 0.0f;
#pragma unroll
        for (int e = 0; e < Ec; e++) { p[e] = __expf(acc[e] - mx); s += p[e]; }
        float inv = 1.0f / s;
        int i1 = 0;
#pragma unroll
        for (int e = 1; e < Ec; e++) if (p[e] > p[i1]) i1 = e;
        int i2 = (i1 == 0) ? 1 : 0;
#pragma unroll
        for (int e = 0; e < Ec; e++) if (e != i1 && p[e] > p[i2]) i2 = e;
        g_topi[2 * n] = i1;     g_topv[2 * n] = p[i1] * inv;
        g_topi[2 * n + 1] = i2; g_topv[2 * n + 1] = p[i2] * inv;
        atomicAdd(&g_cnt[i1], 1);
        atomicAdd(&g_cnt[i2], 1);
    }
}

// ---------------- s1: fused scan + scatter ----------------
__global__ void k_scansc() {
    __shared__ int soff[Ec];
    if (threadIdx.x == 0) {
        int o = 0;
#pragma unroll
        for (int e = 0; e < Ec; e++) {
            soff[e] = o;
            o += ((g_cnt[e] + TMp - 1) / TMp) * TMp;
        }
        if (blockIdx.x == 0) {
#pragma unroll
            for (int e = 0; e < Ec; e++) g_off[e] = soff[e];
            g_off[Ec] = o;
        }
    }
    __syncthreads();
    int n = blockIdx.x * blockDim.x + threadIdx.x;
    if (n >= NT) return;
#pragma unroll
    for (int k = 0; k < 2; k++) {
        int e = g_topi[2 * n + k];
        int pos = soff[e] + atomicAdd(&g_cur[e], 1);
        g_tok[pos] = n;
        g_gate[pos] = g_topv[2 * n + k];
    }
}

// ============ s0: FFN1  h = silu(X@W1) * (X@W3), CTA 128x64, 2 CTA/SM (R13) ============
__global__ void __launch_bounds__(256, 2) k_ffn1() {
    extern __shared__ __half sm[];
    int m0 = blockIdx.y * 128;
    if (m0 >= g_off[Ec]) return;
    int e = 0;
#pragma unroll
    for (int i = 1; i < Ec; i++) if (m0 >= g_off[i]) e = i;
    int n0 = blockIdx.x * 64;

    int tid = threadIdx.x, wid = tid >> 5, lane = tid & 31;
    int wm = wid & 3, wn = wid >> 2;              // warp tile 32 x 32 (dual GEMM)
    int gi = lane >> 2, ti = lane & 3;
    uint32_t smb = smem_u32(sm);

    int rA = tid >> 1, chA = (tid & 1) * 32;      // A: 128 rows x 64 halves
    int rB = tid >> 2, cnB = (tid & 3) * 16;      // B: 64 rows x 64 halves
    int tok = g_tok[m0 + rA];
    const __half* srcA  = g_xh + (size_t)(tok < 0 ? 0 : tok) * Dc + chA;
    const __half* srcB1 = g_w1h + ((size_t)e * Dc + rB) * HP2 + n0 + cnB;
    const __half* srcB3 = g_w3h + ((size_t)e * Dc + rB) * HP2 + n0 + cnB;
    uint32_t dstA  = smb + (uint32_t)(rA * SA1 + chA) * 2;
    uint32_t dstB1 = smb + (uint32_t)(F1_B1OFF + rB * SBF1 + cnB) * 2;
    uint32_t dstB3 = smb + (uint32_t)(F1_B3OFF + rB * SBF1 + cnB) * 2;
    const uint32_t STGB = (uint32_t)F1_STGH * 2;

    auto issue = [&](int kc, int buf) {
        int k0 = kc * KCH;
        uint32_t so = buf * STGB;
        const __half* sA = srcA + k0;
        uint32_t dA = dstA + so;
        CP16(dA, sA); CP16(dA + 16, sA + 8); CP16(dA + 32, sA + 16); CP16(dA + 48, sA + 24);
        const __half* s1 = srcB1 + (size_t)k0 * HP2;
        uint32_t d1 = dstB1 + so;
        CP16(d1, s1); CP16(d1 + 16, s1 + 8);
        const __half* s3 = srcB3 + (size_t)k0 * HP2;
        uint32_t d3 = dstB3 + so;
        CP16(d3, s3); CP16(d3 + 16, s3 + 8);
    };

    int aRow = wm * 32 + (lane & 7) + 8 * ((lane >> 3) & 1);
    uint32_t aBase = smb + (uint32_t)(aRow * SA1 + 8 * (lane >> 4)) * 2;
    int bRowK = (lane & 7) + 8 * ((lane >> 3) & 1);
    uint32_t bBase = smb + (uint32_t)(F1_B1OFF + bRowK * SBF1 + wn * 32 + (lane >> 4) * 8) * 2;
    const uint32_t B3D = (uint32_t)(F1_B3OFF - F1_B1OFF) * 2;   // 9216

    float acc1[2][4][4], acc3[2][4][4];
#pragma unroll
    for (int mt = 0; mt < 2; mt++)
#pragma unroll
        for (int nt = 0; nt < 4; nt++)
#pragma unroll
            for (int j = 0; j < 4; j++) { acc1[mt][nt][j] = 0.f; acc3[mt][nt][j] = 0.f; }

    const int nc = Dc / KCH;   // 16
    issue(0, 0); CP_COMMIT();
    issue(1, 1); CP_COMMIT();

    for (int c = 0; c < nc; ++c) {
        if (c + 1 < nc) CP_WAIT1(); else CP_WAIT0();
        __syncthreads();
        if (c + 2 < nc) { issue(c + 2, (c + 2) % 3); CP_COMMIT(); }
        uint32_t so = (uint32_t)(c % 3) * STGB;
        uint32_t aA = aBase + so;
        uint32_t bB = bBase + so;
#pragma unroll
        for (int ks = 0; ks < 4; ks++) {
            uint32_t af[2][4];
            ldsm_x4(af[0], aA + ks * 32);
            ldsm_x4(af[1], aA + 2304 + ks * 32);        // +16 rows * 144B
#pragma unroll
            for (int np = 0; np < 2; np++) {            // nt pairs
                uint32_t bo = bB + ks * 2304 + np * 32; // +16 k-rows * 144B ; +16 cols
                uint32_t bf1[4], bf3[4];
                ldsm_x4t(bf1, bo);
                ldsm_x4t(bf3, bo + B3D);
                mma16(acc1[0][2 * np],     af[0], bf1);
                mma16(acc1[1][2 * np],     af[1], bf1);
                mma16(acc1[0][2 * np + 1], af[0], bf1 + 2);
                mma16(acc1[1][2 * np + 1], af[1], bf1 + 2);
                mma16(acc3[0][2 * np],     af[0], bf3);
                mma16(acc3[1][2 * np],     af[1], bf3);
                mma16(acc3[0][2 * np + 1], af[0], bf3 + 2);
                mma16(acc3[1][2 * np + 1], af[1], bf3 + 2);
            }
        }
    }

    // epilogue: silu(d1)*d3 -> g_h (fp16)
#pragma unroll
    for (int mt = 0; mt < 2; mt++) {
#pragma unroll
        for (int nt = 0; nt < 4; nt++) {
            int row = m0 + wm * 32 + mt * 16 + gi;
            int col = n0 + wn * 32 + nt * 8 + 2 * ti;
            const float* d1 = acc1[mt][nt];
            const float* d3 = acc3[mt][nt];
            float h0 = d1[0] / (1.0f + __expf(-d1[0])) * d3[0];
            float h1 = d1[1] / (1.0f + __expf(-d1[1])) * d3[1];
            float h2 = d1[2] / (1.0f + __expf(-d1[2])) * d3[2];
            float h3 = d1[3] / (1.0f + __expf(-d1[3])) * d3[3];
            *(__half2*)(g_h + (size_t)row * HP2 + col)       = __floats2half2_rn(h0, h1);
            *(__half2*)(g_h + (size_t)(row + 8) * HP2 + col) = __floats2half2_rn(h2, h3);
        }
    }
}

// ============ s0: FFN2  out += gate * (h @ W2), CTA 128x128, 2 CTA/SM (R13) ============
__global__ void __launch_bounds__(256, 2) k_ffn2(float* __restrict__ out) {
    extern __shared__ __half sm[];
    int m0 = blockIdx.y * 128;
    if (m0 >= g_off[Ec]) return;
    int e = 0;
#pragma unroll
    for (int i = 1; i < Ec; i++) if (m0 >= g_off[i]) e = i;
    int n0 = blockIdx.x * 128;

    int tid = threadIdx.x, wid = tid >> 5, lane = tid & 31;
    int wm = wid & 3, wn = wid >> 2;              // warp tile 32 x 64
    int gi = lane >> 2, ti = lane & 3;
    uint32_t smb = smem_u32(sm);

    int rA = tid >> 1, chA = (tid & 1) * 32;
    int rB = tid >> 2, cnB = (tid & 3) * 32;
    const __half* srcA = g_h + (size_t)(m0 + rA) * HP2 + chA;
    const __half* srcB = g_w2h + ((size_t)e * HP2 + rB) * Dc + n0 + cnB;
    uint32_t dstA = smb + (uint32_t)(rA * SA1 + chA) * 2;
    uint32_t dstB = smb + (uint32_t)(F2_BOFF + rB * SBF2 + cnB) * 2;
    const uint32_t STGB = (uint32_t)F2_STGH * 2;

    auto issue = [&](int kc, int buf) {
        int k0 = kc * KCH;
        uint32_t so = buf * STGB;
        const __half* sA = srcA + k0;
        uint32_t dA = dstA + so;
        CP16(dA, sA); CP16(dA + 16, sA + 8); CP16(dA + 32, sA + 16); CP16(dA + 48, sA + 24);
        const __half* sB = srcB + (size_t)k0 * Dc;
        uint32_t dB = dstB + so;
        CP16(dB, sB); CP16(dB + 16, sB + 8); CP16(dB + 32, sB + 16); CP16(dB + 48, sB + 24);
    };

    int aRow = wm * 32 + (lane & 7) + 8 * ((lane >> 3) & 1);
    uint32_t aBase = smb + (uint32_t)(aRow * SA1 + 8 * (lane >> 4)) * 2;
    int bRowK = (lane & 7) + 8 * ((lane >> 3) & 1);
    uint32_t bBase = smb + (uint32_t)(F2_BOFF + bRowK * SBF2 + wn * 64 + (lane >> 4) * 8) * 2;

    float acc[2][8][4];
#pragma unroll
    for (int mt = 0; mt < 2; mt++)
#pragma unroll
        for (int nt = 0; nt < 8; nt++)
#pragma unroll
            for (int j = 0; j < 4; j++) acc[mt][nt][j] = 0.f;

    const int nc = HP2 / KCH;   // 44
    issue(0, 0); CP_COMMIT();
    issue(1, 1); CP_COMMIT();

    for (int c = 0; c < nc; ++c) {
        if (c + 1 < nc) CP_WAIT1(); else CP_WAIT0();
        __syncthreads();
        if (c + 2 < nc) { issue(c + 2, (c + 2) % 3); CP_COMMIT(); }
        uint32_t so = (uint32_t)(c % 3) * STGB;
        uint32_t aA = aBase + so;
        uint32_t bB = bBase + so;
#pragma unroll
        for (int ks = 0; ks < 4; ks++) {
            uint32_t af[2][4];
            ldsm_x4(af[0], aA + ks * 32);
            ldsm_x4(af[1], aA + 2304 + ks * 32);
#pragma unroll
            for (int np = 0; np < 4; np++) {
                uint32_t bf[4];
                ldsm_x4t(bf, bB + ks * 4352 + np * 32);  // +16 k-rows * 272B ; +16 cols
                mma16(acc[0][2 * np],     af[0], bf);
                mma16(acc[1][2 * np],     af[1], bf);
                mma16(acc[0][2 * np + 1], af[0], bf + 2);
                mma16(acc[1][2 * np + 1], af[1], bf + 2);
            }
        }
    }

    // epilogue: fused combine -> atomicAdd into out[token]
#pragma unroll
    for (int mt = 0; mt < 2; mt++) {
        int row = m0 + wm * 32 + mt * 16 + gi;
        int tok0 = g_tok[row];
        int tok1 = g_tok[row + 8];
        float ga = g_gate[row];
        float gb = g_gate[row + 8];
        float* o0 = out + (size_t)(tok0 < 0 ? 0 : tok0) * Dc;
        float* o1 = out + (size_t)(tok1 < 0 ? 0 : tok1) * Dc;
#pragma unroll
        for (int nt = 0; nt < 8; nt++) {
            int col = n0 + wn * 64 + nt * 8 + 2 * ti;
            const float* d = acc[mt][nt];
            if (tok0 >= 0) {
                atomicAdd(o0 + col,     ga * d[0]);
                atomicAdd(o0 + col + 1, ga * d[1]);
            }
            if (tok1 >= 0) {
                atomicAdd(o1 + col,     gb * d[2]);
                atomicAdd(o1 + col + 1, gb * d[3]);
            }
        }
    }
}

// ---------------- launch: two-stream fork/join ----------------
extern "C" void kernel_launch(void* const* d_in, const int* in_sizes, int n_in,
                              void* d_out, int out_size) {
    const float* x  = (const float*)d_in[0];
    const float* Wr = (const float*)d_in[1];
    const float* W1 = (const float*)d_in[2];
    const float* W2 = (const float*)d_in[3];
    const float* W3 = (const float*)d_in[4];
    float* out = (float*)d_out;

    static cudaStream_t s1 = nullptr;
    static cudaEvent_t e0 = nullptr, e1 = nullptr, e2 = nullptr;
    if (s1 == nullptr) {
        cudaStreamCreateWithFlags(&s1, cudaStreamNonBlocking);
        cudaEventCreateWithFlags(&e0, cudaEventDisableTiming);
        cudaEventCreateWithFlags(&e1, cudaEventDisableTiming);
        cudaEventCreateWithFlags(&e2, cudaEventDisableTiming);
        cudaFuncSetAttribute(k_ffn1, cudaFuncAttributeMaxDynamicSharedMemorySize, F1_SMEM);
        cudaFuncSetAttribute(k_ffn2, cudaFuncAttributeMaxDynamicSharedMemorySize, F2_SMEM);
    }

    // fork: s1 = init -> router -> scansc -> (e1) -> zero(out) -> w2h -> (e2)
    cudaEventRecord(e0, 0);
    cudaStreamWaitEvent(s1, e0, 0);
    k_init<<<(MMAX + 255) / 256, 256, 0, s1>>>();
    k_routerx<<<NT / 8, 256, 0, s1>>>(x, Wr);
    k_scansc<<<NT / 256, 256, 0, s1>>>();
    cudaEventRecord(e1, s1);
    k_zero<<<(NT * Dc / 4) / 256, 256, 0, s1>>>(out);
    k_w2h<<<Ec * HP2, 128, 0, s1>>>(W2);
    cudaEventRecord(e2, s1);

    // s0 = prep13 ; join e1 ; ffn1 ; join e2 ; ffn2
    k_prep13<<<Ec * Dc, 256>>>(W1, W3);
    cudaStreamWaitEvent(0, e1, 0);
    k_ffn1<<<dim3(HP2 / 64, MMAX / 128), 256, F1_SMEM>>>();
    cudaStreamWaitEvent(0, e2, 0);
    k_ffn2<<<dim3(Dc / 128, MMAX / 128), 256, F2_SMEM>>>(out);
}